// round 1
// baseline (speedup 1.0000x reference)
#include <cuda_runtime.h>
#include <cuda_bf16.h>
#include <cstddef>

#define N 4096
#define D 128

// ---------------- scratch (device globals; no allocations allowed) ----------------
__device__ float4 g_uhat[N * D / 4];   // u_hat = h @ W
__device__ float4 g_p[N * D / 4];      // running sum of squash vectors (the "b" low-rank state)
__device__ float4 g_s[N * D / 4];      // s of current routing iteration
__device__ float4 g_sattn[N * D / 4];  // softmax(attn) @ u_hat
__device__ float  g_dis[N];            // 1/sqrt(rowsum(adj)+1e-8)
__device__ float  g_hs[N];             // h @ a_src
__device__ float  g_hd[N];             // h @ a_dst

// ---------------- adj row sums -> d^{-1/2} ----------------
__global__ void rowsum_kernel(const float4* __restrict__ adj4) {
    const int i = blockIdx.x;
    float s = 0.f;
    for (int j = threadIdx.x; j < N / 4; j += 256) {
        float4 a = adj4[(size_t)i * (N / 4) + j];
        s += a.x + a.y + a.z + a.w;
    }
    __shared__ float red[256];
    red[threadIdx.x] = s;
    __syncthreads();
    #pragma unroll
    for (int off = 128; off > 0; off >>= 1) {
        if (threadIdx.x < off) red[threadIdx.x] += red[threadIdx.x + off];
        __syncthreads();
    }
    if (threadIdx.x == 0) g_dis[i] = rsqrtf(red[0] + 1e-8f);
}

// ---------------- u_hat = h @ W  (4 rows per 128-thread block) ----------------
__global__ void uhat_kernel(const float* __restrict__ h, const float* __restrict__ W) {
    __shared__ float hrow[4][128];
    const int t = threadIdx.x;       // 0..127, output dim
    const int i0 = blockIdx.x * 4;
    #pragma unroll
    for (int r = 0; r < 4; r++) hrow[r][t] = h[(size_t)(i0 + r) * D + t];
    __syncthreads();
    float acc[4] = {0.f, 0.f, 0.f, 0.f};
    #pragma unroll 4
    for (int k = 0; k < 128; k++) {
        float wv = W[k * D + t];
        #pragma unroll
        for (int r = 0; r < 4; r++) acc[r] += hrow[r][k] * wv;
    }
    float* uh = reinterpret_cast<float*>(g_uhat);
    #pragma unroll
    for (int r = 0; r < 4; r++) uh[(size_t)(i0 + r) * D + t] = acc[r];
}

// ---------------- hs = h@a_src, hd = h@a_dst  (warp per row) ----------------
__global__ void hsd_kernel(const float4* __restrict__ h4, const float4* __restrict__ a4) {
    const int row  = blockIdx.x * 8 + (threadIdx.x >> 5);
    const int lane = threadIdx.x & 31;
    float4 hv = h4[(size_t)row * 32 + lane];
    float4 as = a4[lane];        // attn_a[0:128]
    float4 ad = a4[32 + lane];   // attn_a[128:256]
    float ps = hv.x * as.x + hv.y * as.y + hv.z * as.z + hv.w * as.w;
    float pd = hv.x * ad.x + hv.y * ad.y + hv.z * ad.z + hv.w * ad.w;
    #pragma unroll
    for (int o = 16; o > 0; o >>= 1) {
        ps += __shfl_xor_sync(0xffffffffu, ps, o);
        pd += __shfl_xor_sync(0xffffffffu, pd, o);
    }
    if (lane == 0) { g_hs[row] = ps; g_hd[row] = pd; }
}

// ---------------- fused flash softmax-matvec ----------------
// MODE 0: score = dis[i]*dis[j]*adj[i,j] + (HAS_P ? p[i].u_hat[j] : 0)   -> writes g_s
// MODE 1: score = leaky_relu(hs[i] + hd[j], 0.2)                         -> writes g_sattn
// Scores are bounded (|score| < ~40) so no online max is needed:
// accumulate unnormalized sum(e) and sum(e*u), divide once at the end.
template <int MODE, bool HAS_P>
__global__ void __launch_bounds__(256, 1)
flash_kernel(const float* __restrict__ adj) {
    __shared__ float4 u_s[32][33];     // padded: conflict-free strided reads
    __shared__ float4 p_s[32][33];
    __shared__ float  adj_s[32][33];
    __shared__ float  prob_s[32][33];
    __shared__ float  lred[8][33];

    const int tid  = threadIdx.x;
    const int lane = tid & 31;     // row within tile (both phases)
    const int w    = tid >> 5;     // warp id: phase A owns cols 4w..4w+3, phase B owns dims 16w..16w+15
    const int i0   = blockIdx.x * 32;
    const int row  = i0 + lane;

    if (HAS_P) {
        #pragma unroll
        for (int m = 0; m < 4; m++) {
            int idx = tid + m * 256;
            p_s[idx >> 5][idx & 31] = g_p[(size_t)(i0 + (idx >> 5)) * 32 + (idx & 31)];
        }
    }
    float di = 0.f, hsi = 0.f;
    if (MODE == 0) di = g_dis[row];
    else           hsi = g_hs[row];

    float4 acc0 = make_float4(0.f, 0.f, 0.f, 0.f);
    float4 acc1 = acc0, acc2 = acc0, acc3 = acc0;
    float lsum = 0.f;

    for (int j0 = 0; j0 < N; j0 += 32) {
        __syncthreads();   // previous tile's phase B done before overwriting u_s / prob_s
        #pragma unroll
        for (int m = 0; m < 4; m++) {
            int idx = tid + m * 256;
            u_s[idx >> 5][idx & 31] = g_uhat[(size_t)(j0 + (idx >> 5)) * 32 + (idx & 31)];
        }
        if (MODE == 0) {
            int tr = tid >> 3, c0 = (tid & 7) << 2;
            float4 av = *reinterpret_cast<const float4*>(adj + (size_t)(i0 + tr) * N + j0 + c0);
            adj_s[tr][c0 + 0] = av.x; adj_s[tr][c0 + 1] = av.y;
            adj_s[tr][c0 + 2] = av.z; adj_s[tr][c0 + 3] = av.w;
        }
        __syncthreads();

        // ---- phase A: scores for (row=lane, cols 4w..4w+3) ----
        float dotv[4] = {0.f, 0.f, 0.f, 0.f};
        if (HAS_P) {
            #pragma unroll 8
            for (int k4 = 0; k4 < 32; k4++) {
                float4 pv = p_s[lane][k4];
                #pragma unroll
                for (int c = 0; c < 4; c++) {
                    float4 uv = u_s[4 * w + c][k4];
                    dotv[c] += pv.x * uv.x;
                    dotv[c] += pv.y * uv.y;
                    dotv[c] += pv.z * uv.z;
                    dotv[c] += pv.w * uv.w;
                }
            }
        }
        #pragma unroll
        for (int c = 0; c < 4; c++) {
            int col = 4 * w + c;
            float sc;
            if (MODE == 0) {
                sc = di * g_dis[j0 + col] * adj_s[lane][col] + dotv[c];
            } else {
                float x = hsi + g_hd[j0 + col];
                sc = (x >= 0.f) ? x : 0.2f * x;
            }
            float e = __expf(sc);
            lsum += e;
            prob_s[lane][col] = e;
        }
        __syncthreads();

        // ---- phase B: acc[row=lane, dims 16w..16w+15] += probs @ u ----
        #pragma unroll 8
        for (int jc = 0; jc < 32; jc++) {
            float pe = prob_s[lane][jc];
            float4 u0 = u_s[jc][4 * w + 0];
            float4 u1 = u_s[jc][4 * w + 1];
            float4 u2 = u_s[jc][4 * w + 2];
            float4 u3 = u_s[jc][4 * w + 3];
            acc0.x += pe * u0.x; acc0.y += pe * u0.y; acc0.z += pe * u0.z; acc0.w += pe * u0.w;
            acc1.x += pe * u1.x; acc1.y += pe * u1.y; acc1.z += pe * u1.z; acc1.w += pe * u1.w;
            acc2.x += pe * u2.x; acc2.y += pe * u2.y; acc2.z += pe * u2.z; acc2.w += pe * u2.w;
            acc3.x += pe * u3.x; acc3.y += pe * u3.y; acc3.z += pe * u3.z; acc3.w += pe * u3.w;
        }
    }

    // ---- combine per-row normalizer across the 8 warps, write s ----
    lred[w][lane] = lsum;
    __syncthreads();
    float lt = 0.f;
    #pragma unroll
    for (int ww = 0; ww < 8; ww++) lt += lred[ww][lane];
    float inv = 1.0f / lt;

    float4* dst = (MODE == 1) ? g_sattn : g_s;
    size_t base = (size_t)row * 32 + 4 * w;
    dst[base + 0] = make_float4(acc0.x * inv, acc0.y * inv, acc0.z * inv, acc0.w * inv);
    dst[base + 1] = make_float4(acc1.x * inv, acc1.y * inv, acc1.z * inv, acc1.w * inv);
    dst[base + 2] = make_float4(acc2.x * inv, acc2.y * inv, acc2.z * inv, acc2.w * inv);
    dst[base + 3] = make_float4(acc3.x * inv, acc3.y * inv, acc3.z * inv, acc3.w * inv);
}

// ---------------- v = squash(s); p (= or +=) v   (warp per row) ----------------
template <bool FIRST>
__global__ void squash_update_kernel() {
    const int idx  = blockIdx.x * 256 + threadIdx.x;
    const int row  = idx >> 5;
    const int lane = idx & 31;
    const size_t o4 = (size_t)row * 32 + lane;
    float4 sv = g_s[o4];
    float nn = sv.x * sv.x + sv.y * sv.y + sv.z * sv.z + sv.w * sv.w;
    #pragma unroll
    for (int o = 16; o > 0; o >>= 1) nn += __shfl_xor_sync(0xffffffffu, nn, o);
    float nrm = sqrtf(nn);
    float f = nrm / ((1.f + nrm) * (nrm + 1e-8f));
    float4 v = make_float4(sv.x * f, sv.y * f, sv.z * f, sv.w * f);
    if (FIRST) {
        g_p[o4] = v;
    } else {
        float4 pp = g_p[o4];
        g_p[o4] = make_float4(pp.x + v.x, pp.y + v.y, pp.z + v.z, pp.w + v.w);
    }
}

// ---------------- out = squash(0.6*s_last + 0.4*s_attn) ----------------
__global__ void final_kernel(float4* __restrict__ out4) {
    const int idx  = blockIdx.x * 256 + threadIdx.x;
    const int row  = idx >> 5;
    const int lane = idx & 31;
    const size_t o4 = (size_t)row * 32 + lane;
    float4 s  = g_s[o4];
    float4 sa = g_sattn[o4];
    float4 c = make_float4(0.6f * s.x + 0.4f * sa.x, 0.6f * s.y + 0.4f * sa.y,
                           0.6f * s.z + 0.4f * sa.z, 0.6f * s.w + 0.4f * sa.w);
    float nn = c.x * c.x + c.y * c.y + c.z * c.z + c.w * c.w;
    #pragma unroll
    for (int o = 16; o > 0; o >>= 1) nn += __shfl_xor_sync(0xffffffffu, nn, o);
    float nrm = sqrtf(nn);
    float f = nrm / ((1.f + nrm) * (nrm + 1e-8f));
    out4[o4] = make_float4(c.x * f, c.y * f, c.z * f, c.w * f);
}

// ---------------- launch ----------------
extern "C" void kernel_launch(void* const* d_in, const int* in_sizes, int n_in,
                              void* d_out, int out_size) {
    (void)in_sizes; (void)n_in; (void)out_size;
    const float* h      = (const float*)d_in[0];
    const float* adj    = (const float*)d_in[1];
    const float* W      = (const float*)d_in[2];
    const float* attn_a = (const float*)d_in[3];
    float* out = (float*)d_out;

    rowsum_kernel<<<N, 256>>>((const float4*)adj);
    uhat_kernel<<<N / 4, 128>>>(h, W);
    hsd_kernel<<<N / 8, 256>>>((const float4*)h, (const float4*)attn_a);

    // routing iteration 0 (p = 0 -> bias-only scores)
    flash_kernel<0, false><<<N / 32, 256>>>(adj);
    squash_update_kernel<true><<<N / 8, 256>>>();
    // iteration 1
    flash_kernel<0, true><<<N / 32, 256>>>(adj);
    squash_update_kernel<false><<<N / 8, 256>>>();
    // iteration 2 (s kept in g_s; its v is never used)
    flash_kernel<0, true><<<N / 32, 256>>>(adj);

    // attention branch: softmax(leaky_relu(hs[i]+hd[j])) @ u_hat
    flash_kernel<1, false><<<N / 32, 256>>>(adj);

    final_kernel<<<N / 8, 256>>>((float4*)out);
}

// round 2
// speedup vs baseline: 4.3821x; 4.3821x over previous
#include <cuda_runtime.h>
#include <cuda_bf16.h>
#include <cstdint>
#include <cstddef>

#define N 4096
#define D 128
#define CHUNKS 8
#define JT 64
#define TILES_PER_CHUNK ((N / CHUNKS) / JT)   // 8
#define PITCH 272                              // bytes per padded smem row (136 bf16)
#define TILE_BYTES (64 * PITCH)                // 17408

// ---------------- device scratch ----------------
__device__ __nv_bfloat16 g_u_hi[N * D], g_u_lo[N * D];
__device__ __nv_bfloat16 g_p_hi[N * D], g_p_lo[N * D];
__device__ float g_pf[N * D];
__device__ float g_partA[(size_t)CHUNKS * N * D];
__device__ float g_partB[(size_t)CHUNKS * N * D];
__device__ float g_plsumA[CHUNKS * N], g_plsumB[CHUNKS * N];
__device__ float g_dis[N], g_hs[N], g_hd[N];

// ---------------- helpers ----------------
__device__ __forceinline__ uint32_t pack2(float lo, float hi) {
    uint32_t d;
    asm("cvt.rn.bf16x2.f32 %0, %1, %2;" : "=r"(d) : "f"(hi), "f"(lo));
    return d;
}
__device__ __forceinline__ void mma_bf16(float* c, const uint32_t* a, uint32_t b0, uint32_t b1) {
    asm volatile(
        "mma.sync.aligned.m16n8k16.row.col.f32.bf16.bf16.f32 "
        "{%0,%1,%2,%3},{%4,%5,%6,%7},{%8,%9},{%0,%1,%2,%3};"
        : "+f"(c[0]), "+f"(c[1]), "+f"(c[2]), "+f"(c[3])
        : "r"(a[0]), "r"(a[1]), "r"(a[2]), "r"(a[3]), "r"(b0), "r"(b1));
}
#define LDSM4(r, addr)                                                              \
    asm volatile("ldmatrix.sync.aligned.m8n8.x4.shared.b16 {%0,%1,%2,%3},[%4];"     \
                 : "=r"((r)[0]), "=r"((r)[1]), "=r"((r)[2]), "=r"((r)[3]) : "r"(addr))
#define LDSM4T(r, addr)                                                                  \
    asm volatile("ldmatrix.sync.aligned.m8n8.x4.trans.shared.b16 {%0,%1,%2,%3},[%4];"    \
                 : "=r"((r)[0]), "=r"((r)[1]), "=r"((r)[2]), "=r"((r)[3]) : "r"(addr))

// ---------------- adj row sums -> d^{-1/2} ----------------
__global__ void rowsum_kernel(const float4* __restrict__ adj4) {
    const int i = blockIdx.x;
    float s = 0.f;
    for (int j = threadIdx.x; j < N / 4; j += 256) {
        float4 a = adj4[(size_t)i * (N / 4) + j];
        s += a.x + a.y + a.z + a.w;
    }
    __shared__ float red[256];
    red[threadIdx.x] = s;
    __syncthreads();
    #pragma unroll
    for (int off = 128; off > 0; off >>= 1) {
        if (threadIdx.x < off) red[threadIdx.x] += red[threadIdx.x + off];
        __syncthreads();
    }
    if (threadIdx.x == 0) g_dis[i] = rsqrtf(red[0] + 1e-8f);
}

// ---------------- u_hat = h @ W, split into bf16 hi/lo ----------------
__global__ void uhat_kernel(const float* __restrict__ h, const float* __restrict__ W) {
    __shared__ float hrow[4][128];
    const int t = threadIdx.x;
    const int i0 = blockIdx.x * 4;
    #pragma unroll
    for (int r = 0; r < 4; r++) hrow[r][t] = h[(size_t)(i0 + r) * D + t];
    __syncthreads();
    float acc[4] = {0.f, 0.f, 0.f, 0.f};
    #pragma unroll 4
    for (int k = 0; k < 128; k++) {
        float wv = W[k * D + t];
        #pragma unroll
        for (int r = 0; r < 4; r++) acc[r] += hrow[r][k] * wv;
    }
    #pragma unroll
    for (int r = 0; r < 4; r++) {
        __nv_bfloat16 hi = __float2bfloat16_rn(acc[r]);
        float hf = __bfloat162float(hi);
        g_u_hi[(size_t)(i0 + r) * D + t] = hi;
        g_u_lo[(size_t)(i0 + r) * D + t] = __float2bfloat16_rn(acc[r] - hf);
    }
}

// ---------------- hs = h@a_src, hd = h@a_dst ----------------
__global__ void hsd_kernel(const float4* __restrict__ h4, const float4* __restrict__ a4) {
    const int row  = blockIdx.x * 8 + (threadIdx.x >> 5);
    const int lane = threadIdx.x & 31;
    float4 hv = h4[(size_t)row * 32 + lane];
    float4 as = a4[lane];
    float4 ad = a4[32 + lane];
    float ps = hv.x * as.x + hv.y * as.y + hv.z * as.z + hv.w * as.w;
    float pd = hv.x * ad.x + hv.y * ad.y + hv.z * ad.z + hv.w * ad.w;
    #pragma unroll
    for (int o = 16; o > 0; o >>= 1) {
        ps += __shfl_xor_sync(0xffffffffu, ps, o);
        pd += __shfl_xor_sync(0xffffffffu, pd, o);
    }
    if (lane == 0) { g_hs[row] = ps; g_hd[row] = pd; }
}

// ---------------- tensor-core flash: partial unnormalized softmax @ u ----------------
// MODE 0: score = dis_i*dis_j*adj[i,j] + (HAS_P ? p_i . u_j : 0)   -> g_partA
// MODE 1: score = leaky_relu(hs_i + hd_j)                          -> g_partB
template <int MODE, bool HAS_P>
__global__ void __launch_bounds__(128, 3)
flash_mma(const float* __restrict__ adj) {
    extern __shared__ char sm[];
    __nv_bfloat16* u_hi_s = (__nv_bfloat16*)(sm);
    __nv_bfloat16* u_lo_s = (__nv_bfloat16*)(sm + TILE_BYTES);
    __nv_bfloat16* p_hi_s = (__nv_bfloat16*)(sm + 2 * TILE_BYTES);
    __nv_bfloat16* p_lo_s = (__nv_bfloat16*)(sm + 3 * TILE_BYTES);
    float* aux_s = (float*)(sm + (HAS_P ? 4 : 2) * TILE_BYTES);

    float* part  = (MODE == 1) ? g_partB  : g_partA;
    float* plsum = (MODE == 1) ? g_plsumB : g_plsumA;

    const int tid  = threadIdx.x;
    const int wid  = tid >> 5;
    const int lane = tid & 31;
    const int gid  = lane >> 2, tig = lane & 3;
    const int rb = blockIdx.x, chunk = blockIdx.y;
    const int r  = rb * 64 + wid * 16 + gid;
    const int r2 = r + 8;
    const int jbase = chunk * (N / CHUNKS);

    const uint32_t sm0 = (uint32_t)__cvta_generic_to_shared(sm);
    const uint32_t uhi_b = sm0, ulo_b = sm0 + TILE_BYTES;
    const uint32_t phi_b = sm0 + 2 * TILE_BYTES, plo_b = sm0 + 3 * TILE_BYTES;

    const int l7 = lane & 7;
    const int sA_off  = (((lane >> 3) & 1) * 8 + l7) * PITCH + ((lane >> 4) & 1) * 16;
    const int sBn_off = (((lane >> 4) & 1) * 8 + l7) * PITCH + ((lane >> 3) & 1) * 16;
    const int sBt_off = (((lane >> 3) & 1) * 8 + l7) * PITCH + ((lane >> 4) & 1) * 16;

    // stage p tile (rows of this CTA) once
    if (HAS_P) {
        for (int k = tid; k < 64 * 16; k += 128) {
            int row = k >> 4, c16 = k & 15;
            *(uint4*)((char*)p_hi_s + row * PITCH + c16 * 16) =
                *(const uint4*)(g_p_hi + (size_t)(rb * 64 + row) * D + c16 * 8);
            *(uint4*)((char*)p_lo_s + row * PITCH + c16 * 16) =
                *(const uint4*)(g_p_lo + (size_t)(rb * 64 + row) * D + c16 * 8);
        }
    }

    float di_r = 0.f, di_r2 = 0.f, hs_r = 0.f, hs_r2 = 0.f;
    if (MODE == 0) { di_r = g_dis[r]; di_r2 = g_dis[r2]; }
    else           { hs_r = g_hs[r];  hs_r2 = g_hs[r2]; }

    float acc[16][4];
    #pragma unroll
    for (int i = 0; i < 16; i++)
        #pragma unroll
        for (int k = 0; k < 4; k++) acc[i][k] = 0.f;
    float lr = 0.f, lr2 = 0.f;

    #pragma unroll 1
    for (int t = 0; t < TILES_PER_CHUNK; t++) {
        const int j0 = jbase + t * JT;
        __syncthreads();
        for (int k = tid; k < 64 * 16; k += 128) {
            int row = k >> 4, c16 = k & 15;
            *(uint4*)((char*)u_hi_s + row * PITCH + c16 * 16) =
                *(const uint4*)(g_u_hi + (size_t)(j0 + row) * D + c16 * 8);
            *(uint4*)((char*)u_lo_s + row * PITCH + c16 * 16) =
                *(const uint4*)(g_u_lo + (size_t)(j0 + row) * D + c16 * 8);
        }
        if (tid < 64) aux_s[tid] = (MODE == 0) ? g_dis[j0 + tid] : g_hd[j0 + tid];
        __syncthreads();

        // ---- phase A: S = P . U^T (split bf16, 3 passes) ----
        float S[8][4];
        if (HAS_P) {
            #pragma unroll
            for (int i = 0; i < 8; i++)
                #pragma unroll
                for (int k = 0; k < 4; k++) S[i][k] = 0.f;
            #pragma unroll
            for (int kt = 0; kt < 8; kt++) {
                uint32_t ph[4], pl[4];
                LDSM4(ph, phi_b + wid * 16 * PITCH + 32 * kt + sA_off);
                LDSM4(pl, plo_b + wid * 16 * PITCH + 32 * kt + sA_off);
                #pragma unroll
                for (int jp = 0; jp < 4; jp++) {
                    uint32_t bh[4], bl[4];
                    uint32_t off = 16 * jp * PITCH + 32 * kt + sBn_off;
                    LDSM4(bh, uhi_b + off);
                    LDSM4(bl, ulo_b + off);
                    mma_bf16(S[2 * jp],     ph, bh[0], bh[1]);
                    mma_bf16(S[2 * jp + 1], ph, bh[2], bh[3]);
                    mma_bf16(S[2 * jp],     ph, bl[0], bl[1]);
                    mma_bf16(S[2 * jp + 1], ph, bl[2], bl[3]);
                    mma_bf16(S[2 * jp],     pl, bh[0], bh[1]);
                    mma_bf16(S[2 * jp + 1], pl, bh[2], bh[3]);
                }
            }
        }

        // ---- exp + repack into A-fragments (hi/lo) ----
        uint32_t ahi[4][4], alo[4][4];
        #pragma unroll
        for (int kp = 0; kp < 4; kp++) {
            #pragma unroll
            for (int half = 0; half < 2; half++) {
                const int jn = 2 * kp + half;
                const int c = 8 * jn + 2 * tig;
                float e00, e01, e10, e11;
                if (MODE == 0) {
                    float djc0 = aux_s[c], djc1 = aux_s[c + 1];
                    float2 a_r  = __ldg((const float2*)(adj + (size_t)r  * N + j0 + c));
                    float2 a_r2 = __ldg((const float2*)(adj + (size_t)r2 * N + j0 + c));
                    float b00 = di_r  * djc0 * a_r.x,  b01 = di_r  * djc1 * a_r.y;
                    float b10 = di_r2 * djc0 * a_r2.x, b11 = di_r2 * djc1 * a_r2.y;
                    if (HAS_P) {
                        b00 += S[jn][0]; b01 += S[jn][1];
                        b10 += S[jn][2]; b11 += S[jn][3];
                    }
                    e00 = __expf(b00); e01 = __expf(b01);
                    e10 = __expf(b10); e11 = __expf(b11);
                } else {
                    float hd0 = aux_s[c], hd1 = aux_s[c + 1];
                    float x00 = hs_r + hd0,  x01 = hs_r + hd1;
                    float x10 = hs_r2 + hd0, x11 = hs_r2 + hd1;
                    x00 = (x00 >= 0.f) ? x00 : 0.2f * x00;
                    x01 = (x01 >= 0.f) ? x01 : 0.2f * x01;
                    x10 = (x10 >= 0.f) ? x10 : 0.2f * x10;
                    x11 = (x11 >= 0.f) ? x11 : 0.2f * x11;
                    e00 = __expf(x00); e01 = __expf(x01);
                    e10 = __expf(x10); e11 = __expf(x11);
                }
                lr  += e00 + e01;
                lr2 += e10 + e11;
                uint32_t h0 = pack2(e00, e01);
                uint32_t h1 = pack2(e10, e11);
                float f00 = __uint_as_float(h0 << 16), f01 = __uint_as_float(h0 & 0xffff0000u);
                float f10 = __uint_as_float(h1 << 16), f11 = __uint_as_float(h1 & 0xffff0000u);
                ahi[kp][2 * half + 0] = h0;
                ahi[kp][2 * half + 1] = h1;
                alo[kp][2 * half + 0] = pack2(e00 - f00, e01 - f01);
                alo[kp][2 * half + 1] = pack2(e10 - f10, e11 - f11);
            }
        }

        // ---- phase B: ACC += PROB . U (split bf16, 3 passes) ----
        #pragma unroll
        for (int kp = 0; kp < 4; kp++) {
            #pragma unroll
            for (int dn2 = 0; dn2 < 8; dn2++) {
                uint32_t bh[4], bl[4];
                uint32_t off = 16 * kp * PITCH + 32 * dn2 + sBt_off;
                LDSM4T(bh, uhi_b + off);
                LDSM4T(bl, ulo_b + off);
                mma_bf16(acc[2 * dn2],     ahi[kp], bh[0], bh[1]);
                mma_bf16(acc[2 * dn2 + 1], ahi[kp], bh[2], bh[3]);
                mma_bf16(acc[2 * dn2],     ahi[kp], bl[0], bl[1]);
                mma_bf16(acc[2 * dn2 + 1], ahi[kp], bl[2], bl[3]);
                mma_bf16(acc[2 * dn2],     alo[kp], bh[0], bh[1]);
                mma_bf16(acc[2 * dn2 + 1], alo[kp], bh[2], bh[3]);
            }
        }
    }

    // ---- write partial lsum + partial sums ----
    lr  += __shfl_xor_sync(0xffffffffu, lr, 1);
    lr  += __shfl_xor_sync(0xffffffffu, lr, 2);
    lr2 += __shfl_xor_sync(0xffffffffu, lr2, 1);
    lr2 += __shfl_xor_sync(0xffffffffu, lr2, 2);
    if (tig == 0) {
        plsum[chunk * N + r]  = lr;
        plsum[chunk * N + r2] = lr2;
    }
    #pragma unroll
    for (int dn = 0; dn < 16; dn++) {
        size_t o1 = ((size_t)chunk * N + r) * D + 8 * dn + 2 * tig;
        size_t o2 = ((size_t)chunk * N + r2) * D + 8 * dn + 2 * tig;
        *(float2*)(part + o1) = make_float2(acc[dn][0], acc[dn][1]);
        *(float2*)(part + o2) = make_float2(acc[dn][2], acc[dn][3]);
    }
}

// ---------------- reduce chunks, normalize, squash, update p ----------------
template <bool FIRST>
__global__ void reduce_squash_kernel() {
    const int row  = (blockIdx.x * 256 + threadIdx.x) >> 5;
    const int lane = threadIdx.x & 31;
    float4 s4 = make_float4(0.f, 0.f, 0.f, 0.f);
    float ls = 0.f;
    #pragma unroll
    for (int c = 0; c < CHUNKS; c++) {
        const float4 v = *(const float4*)(g_partA + ((size_t)c * N + row) * D + lane * 4);
        s4.x += v.x; s4.y += v.y; s4.z += v.z; s4.w += v.w;
        ls += g_plsumA[c * N + row];
    }
    float inv = 1.f / ls;
    s4.x *= inv; s4.y *= inv; s4.z *= inv; s4.w *= inv;
    float nn = s4.x * s4.x + s4.y * s4.y + s4.z * s4.z + s4.w * s4.w;
    #pragma unroll
    for (int o = 16; o > 0; o >>= 1) nn += __shfl_xor_sync(0xffffffffu, nn, o);
    float nrm = sqrtf(nn);
    float f = nrm / ((1.f + nrm) * (nrm + 1e-8f));
    float4 p;
    if (FIRST) {
        p = make_float4(f * s4.x, f * s4.y, f * s4.z, f * s4.w);
    } else {
        const float4 po = *(const float4*)(g_pf + (size_t)row * D + lane * 4);
        p = make_float4(po.x + f * s4.x, po.y + f * s4.y, po.z + f * s4.z, po.w + f * s4.w);
    }
    *(float4*)(g_pf + (size_t)row * D + lane * 4) = p;
    uint32_t h01 = pack2(p.x, p.y), h23 = pack2(p.z, p.w);
    *(uint32_t*)(g_p_hi + (size_t)row * D + lane * 4)     = h01;
    *(uint32_t*)(g_p_hi + (size_t)row * D + lane * 4 + 2) = h23;
    float fx = __uint_as_float(h01 << 16), fy = __uint_as_float(h01 & 0xffff0000u);
    float fz = __uint_as_float(h23 << 16), fw = __uint_as_float(h23 & 0xffff0000u);
    *(uint32_t*)(g_p_lo + (size_t)row * D + lane * 4)     = pack2(p.x - fx, p.y - fy);
    *(uint32_t*)(g_p_lo + (size_t)row * D + lane * 4 + 2) = pack2(p.z - fz, p.w - fw);
}

// ---------------- out = squash(0.6*s_route + 0.4*s_attn) ----------------
__global__ void final_kernel(float* __restrict__ out) {
    const int row  = (blockIdx.x * 256 + threadIdx.x) >> 5;
    const int lane = threadIdx.x & 31;
    float4 sa = make_float4(0.f, 0.f, 0.f, 0.f);
    float4 sb = sa;
    float la = 0.f, lb = 0.f;
    #pragma unroll
    for (int c = 0; c < CHUNKS; c++) {
        const float4 va = *(const float4*)(g_partA + ((size_t)c * N + row) * D + lane * 4);
        const float4 vb = *(const float4*)(g_partB + ((size_t)c * N + row) * D + lane * 4);
        sa.x += va.x; sa.y += va.y; sa.z += va.z; sa.w += va.w;
        sb.x += vb.x; sb.y += vb.y; sb.z += vb.z; sb.w += vb.w;
        la += g_plsumA[c * N + row];
        lb += g_plsumB[c * N + row];
    }
    float ia = 0.6f / la, ib = 0.4f / lb;
    float4 cm = make_float4(sa.x * ia + sb.x * ib, sa.y * ia + sb.y * ib,
                            sa.z * ia + sb.z * ib, sa.w * ia + sb.w * ib);
    float nn = cm.x * cm.x + cm.y * cm.y + cm.z * cm.z + cm.w * cm.w;
    #pragma unroll
    for (int o = 16; o > 0; o >>= 1) nn += __shfl_xor_sync(0xffffffffu, nn, o);
    float nrm = sqrtf(nn);
    float f = nrm / ((1.f + nrm) * (nrm + 1e-8f));
    *(float4*)(out + (size_t)row * D + lane * 4) =
        make_float4(cm.x * f, cm.y * f, cm.z * f, cm.w * f);
}

// ---------------- launch ----------------
extern "C" void kernel_launch(void* const* d_in, const int* in_sizes, int n_in,
                              void* d_out, int out_size) {
    (void)in_sizes; (void)n_in; (void)out_size;
    const float* h      = (const float*)d_in[0];
    const float* adj    = (const float*)d_in[1];
    const float* W      = (const float*)d_in[2];
    const float* attn_a = (const float*)d_in[3];
    float* out = (float*)d_out;

    static const size_t SMEM_NOP = 2 * TILE_BYTES + 256;   // 35072
    static const size_t SMEM_P   = 4 * TILE_BYTES + 256;   // 69888
    cudaFuncSetAttribute(flash_mma<0, true>,
                         cudaFuncAttributeMaxDynamicSharedMemorySize, (int)SMEM_P);

    rowsum_kernel<<<N, 256>>>((const float4*)adj);
    uhat_kernel<<<N / 4, 128>>>(h, W);
    hsd_kernel<<<N / 8, 256>>>((const float4*)h, (const float4*)attn_a);

    dim3 fg(N / 64, CHUNKS);
    // iteration 0: bias-only scores
    flash_mma<0, false><<<fg, 128, SMEM_NOP>>>(adj);
    reduce_squash_kernel<true><<<N / 8, 256>>>();
    // iteration 1
    flash_mma<0, true><<<fg, 128, SMEM_P>>>(adj);
    reduce_squash_kernel<false><<<N / 8, 256>>>();
    // iteration 2 (partials kept; consumed by final)
    flash_mma<0, true><<<fg, 128, SMEM_P>>>(adj);

    // attention branch
    flash_mma<1, false><<<fg, 128, SMEM_NOP>>>(adj);

    final_kernel<<<N / 8, 256>>>(out);
}